// round 11
// baseline (speedup 1.0000x reference)
#include <cuda_runtime.h>
#include <cuda_fp16.h>
#include <cstdint>
#include <math.h>

// Problem constants
constexpr int Bc  = 8;
constexpr int Sc  = 512;
constexpr int Ec  = 1024;
constexpr int Hc  = 16;
constexpr int HDc = 64;
constexpr int FFc = 4096;
constexpr int NEc = 129;           // 2P+1
constexpr int Mc  = Bc * Sc;       // 4096 rows
constexpr int E3  = 3 * Ec;        // 3072
constexpr int SE  = 672;           // extended score width: 512 + 129 + pad

// ---------------------------------------------------------------------------
// Scratch (device globals; no allocation allowed)
// ---------------------------------------------------------------------------
__device__ __align__(256) __half g_xh[Mc * Ec];
__device__ __align__(256) __half g_W3h[E3 * Ec];
__device__ __align__(256) __half g_Woh[Ec * Ec];
__device__ __align__(256) __half g_W1h[FFc * Ec];
__device__ __align__(256) __half g_W2h[Ec * FFc];
__device__ float g_b3[E3];
__device__ __align__(256) __half g_qkvh[Mc * E3];
__device__ __align__(256) __half g_peh[256 * HDc];
__device__ float g_aw[128 * Sc * SE];                  // fp32 scores
__device__ __align__(256) __half g_awh[128 * Sc * SE];
__device__ __align__(256) __half g_vth[128 * HDc * SE];
__device__ __align__(256) __half g_ah[Mc * Ec];
__device__ float g_t0[Mc * Ec];
__device__ float g_h[Mc * Ec];
__device__ __align__(256) __half g_hh[Mc * Ec];
__device__ __align__(256) __half g_fh[Mc * FFc];

// ---------------------------------------------------------------------------
// PTX helpers
// ---------------------------------------------------------------------------
__device__ __forceinline__ uint32_t smem_u32(const void* p) {
    uint32_t a;
    asm("{ .reg .u64 t; cvta.to.shared.u64 t, %1; cvt.u32.u64 %0, t; }" : "=r"(a) : "l"(p));
    return a;
}
__device__ __forceinline__ void cpasync16(uint32_t dst, const void* src) {
    asm volatile("cp.async.cg.shared.global [%0], [%1], 16;" :: "r"(dst), "l"(src));
}
#define CP_COMMIT()  asm volatile("cp.async.commit_group;" ::: "memory")
#define CP_WAIT(n)   asm volatile("cp.async.wait_group %0;" :: "n"(n) : "memory")

__device__ __forceinline__ void ldsm4(uint32_t* r, uint32_t addr) {
    asm volatile("ldmatrix.sync.aligned.m8n8.x4.shared.b16 {%0,%1,%2,%3}, [%4];"
                 : "=r"(r[0]), "=r"(r[1]), "=r"(r[2]), "=r"(r[3]) : "r"(addr));
}
__device__ __forceinline__ void mma_f16(float* c, const uint32_t* a, const uint32_t* b) {
    asm volatile(
        "mma.sync.aligned.m16n8k16.row.col.f32.f16.f16.f32 "
        "{%0,%1,%2,%3}, {%4,%5,%6,%7}, {%8,%9}, {%0,%1,%2,%3};"
        : "+f"(c[0]), "+f"(c[1]), "+f"(c[2]), "+f"(c[3])
        : "r"(a[0]), "r"(a[1]), "r"(a[2]), "r"(a[3]), "r"(b[0]), "r"(b[1]));
}
__device__ __forceinline__ uint32_t pack2(float v0, float v1) {
    __half2 ph = __halves2half2(__float2half_rn(v0), __float2half_rn(v1));
    return *(uint32_t*)&ph;
}

// ---------------------------------------------------------------------------
// HMMA GEMM (single-pass, BK=64): C[M,N] = Ah[M,K] @ Bh[N,K]^T + bias
// 128x128 CTA tile, 8 warps of 32x64. 3-stage cp.async pipeline,
// ONE __syncthreads per 64-wide K-chunk.
// ---------------------------------------------------------------------------
constexpr int LDS64  = 72;                   // padded row (elems): 64 + 8
constexpr int TILE64 = 128 * LDS64 * 2;      // 18432 B
constexpr int BUF64  = 2 * TILE64;           // A,B = 36864
constexpr int MMA_SMEM = 3 * BUF64;          // 110592 B

template<int RELU, int EMITH>
__global__ void __launch_bounds__(256)
mma_gemm(const __half* __restrict__ Ah, const __half* __restrict__ Bh,
         const float* __restrict__ bias, float* __restrict__ C,
         __half* __restrict__ Ch, int K, int N)
{
    extern __shared__ char sm[];
    const uint32_t sbase = smem_u32(sm);
    const int tid = threadIdx.x;
    const int wid = tid >> 5, lane = tid & 31;
    const int wm = wid & 3, wn = wid >> 2;
    const int bm = blockIdx.y * 128, bn = blockIdx.x * 128;
    const int nk = K >> 6;                     // 64-wide chunks

    // loader coords: 2 threads per row, 64B (4x16B) per thread per tile
    const int lr = tid >> 1;                   // row 0..127
    const int lc = (tid & 1) << 6;             // elem col 0 or 64... (of 64: 0|32)
    // NOTE: row has 64 elems = 128B; two threads each copy 64B (4 cp.async16)
    const int lce = (tid & 1) * 32;            // elem offset: 0 or 32

    auto load_chunk = [&](int kc) {
        if (kc < nk) {
            const uint32_t base = sbase + (kc % 3) * BUF64;
            const int k0 = kc << 6;
            #pragma unroll
            for (int j = 0; j < 4; j++) {
                const int ce = lce + j * 8;    // 8 elems = 16B per cp
                const uint32_t off = (lr * LDS64 + ce) * 2;
                cpasync16(base + off,          Ah + (size_t)(bm + lr) * K + k0 + ce);
                cpasync16(base + TILE64 + off, Bh + (size_t)(bn + lr) * K + k0 + ce);
            }
        }
        CP_COMMIT();
    };
    (void)lc;

    float acc[2][8][4];
    #pragma unroll
    for (int mt = 0; mt < 2; mt++)
        #pragma unroll
        for (int nt = 0; nt < 8; nt++)
            #pragma unroll
            for (int i = 0; i < 4; i++) acc[mt][nt][i] = 0.f;

    uint32_t aF[2][2][4];
    uint32_t bF[8][2][2];

    const int a_row = wm * 32 + (lane & 15);
    const int a_kof = (lane >> 4) << 3;
    const int b_n   = wn * 64 + (lane & 7) + ((lane & 16) >> 1);
    const int b_kof = ((lane >> 3) & 1) << 3;

    auto loadA = [&](uint32_t tbase, int k0) {
        #pragma unroll
        for (int mt = 0; mt < 2; mt++)
            #pragma unroll
            for (int ks = 0; ks < 2; ks++)
                ldsm4(aF[mt][ks], tbase + ((a_row + mt * 16) * LDS64 + k0 + ks * 16 + a_kof) * 2);
    };
    auto loadB = [&](uint32_t tbase, int k0) {
        #pragma unroll
        for (int ntp = 0; ntp < 4; ntp++)
            #pragma unroll
            for (int ks = 0; ks < 2; ks++) {
                uint32_t t4[4];
                ldsm4(t4, tbase + ((b_n + ntp * 16) * LDS64 + k0 + ks * 16 + b_kof) * 2);
                bF[ntp * 2 + 0][ks][0] = t4[0]; bF[ntp * 2 + 0][ks][1] = t4[1];
                bF[ntp * 2 + 1][ks][0] = t4[2]; bF[ntp * 2 + 1][ks][1] = t4[3];
            }
    };
    auto mma_all = [&]() {
        #pragma unroll
        for (int ks = 0; ks < 2; ks++)
            #pragma unroll
            for (int mt = 0; mt < 2; mt++)
                #pragma unroll
                for (int nt = 0; nt < 8; nt++)
                    mma_f16(acc[mt][nt], aF[mt][ks], bF[nt][ks]);
    };

    load_chunk(0);
    load_chunk(1);
    for (int kc = 0; kc < nk; kc++) {
        CP_WAIT(1);
        __syncthreads();
        load_chunk(kc + 2);

        const uint32_t base = sbase + (kc % 3) * BUF64;
        #pragma unroll
        for (int half = 0; half < 2; half++) {
            loadA(base, half * 32);
            loadB(base + TILE64, half * 32);
            mma_all();
        }
    }

    #pragma unroll
    for (int mt = 0; mt < 2; mt++) {
        #pragma unroll
        for (int nt = 0; nt < 8; nt++) {
            const int row = bm + wm * 32 + mt * 16 + (lane >> 2);
            const int col = bn + wn * 64 + nt * 8 + ((lane & 3) << 1);
            const float bi0 = bias[col], bi1 = bias[col + 1];
            float o00 = acc[mt][nt][0] + bi0, o01 = acc[mt][nt][1] + bi1;
            float o10 = acc[mt][nt][2] + bi0, o11 = acc[mt][nt][3] + bi1;
            if (RELU) {
                o00 = fmaxf(o00, 0.f); o01 = fmaxf(o01, 0.f);
                o10 = fmaxf(o10, 0.f); o11 = fmaxf(o11, 0.f);
            }
            const size_t i0 = (size_t)row * N + col;
            const size_t i1 = (size_t)(row + 8) * N + col;
            if (EMITH) {
                *(uint32_t*)(Ch + i0) = pack2(o00, o01);
                *(uint32_t*)(Ch + i1) = pack2(o10, o11);
            } else {
                *(float2*)(C + i0) = make_float2(o00, o01);
                *(float2*)(C + i1) = make_float2(o10, o11);
            }
        }
    }
}

// ---------------------------------------------------------------------------
// Fused scores GEMM (HMMA, single-pass): per (b,h):
//   AW[i, j]     = Q_h[i,:] . K_h[j,:]       (j < 512)
//   AW[i, 512+e] = Q_h[i,:] . pos_emb[e,:]   (e < 129; pad rows zero)
// ---------------------------------------------------------------------------
constexpr int QK_LDS = 72;
constexpr int QK_T   = 128 * QK_LDS * 2;     // 18432
constexpr int QK_SMEM = 2 * QK_T;            // 36864 B

__global__ void __launch_bounds__(256)
qk_scores(float* __restrict__ AW)
{
    extern __shared__ char sm[];
    const uint32_t sA = smem_u32(sm);
    const uint32_t sB = sA + QK_T;
    const int tid = threadIdx.x;
    const int wid = tid >> 5, lane = tid & 31;
    const int wm = wid & 3, wn = wid >> 2;
    const int bn = blockIdx.x * 128, bm = blockIdx.y * 128;
    const int bh = blockIdx.z, b = bh >> 4, h = bh & 15;

    {
        const int r0 = tid >> 3, sg = (tid & 7) << 3;
        #pragma unroll
        for (int it = 0; it < 4; it++) {
            const int r = r0 + it * 32;
            const uint32_t off = (r * QK_LDS + sg) * 2;
            cpasync16(sA + off, g_qkvh + (size_t)(b * Sc + bm + r) * E3 + h * HDc + sg);
            const int gr = bn + r;
            const __half* bph;
            if (gr < Sc) {
                bph = g_qkvh + (size_t)(b * Sc + gr) * E3 + Ec + h * HDc + sg;
            } else {
                bph = g_peh + (size_t)(gr - Sc) * HDc + sg;
            }
            cpasync16(sB + off, bph);
        }
        CP_COMMIT(); CP_WAIT(0);
        __syncthreads();
    }

    float acc[2][8][4];
    #pragma unroll
    for (int mt = 0; mt < 2; mt++)
        #pragma unroll
        for (int nt = 0; nt < 8; nt++)
            #pragma unroll
            for (int i = 0; i < 4; i++) acc[mt][nt][i] = 0.f;

    uint32_t aF[2][2][4], bF[8][2][2];
    const int a_row = wm * 32 + (lane & 15);
    const int a_kof = (lane >> 4) << 3;
    const int b_n   = wn * 64 + (lane & 7) + ((lane & 16) >> 1);
    const int b_kof = ((lane >> 3) & 1) << 3;

    auto loadA = [&](int k0) {
        #pragma unroll
        for (int mt = 0; mt < 2; mt++)
            #pragma unroll
            for (int ks = 0; ks < 2; ks++)
                ldsm4(aF[mt][ks], sA + ((a_row + mt * 16) * QK_LDS + k0 + ks * 16 + a_kof) * 2);
    };
    auto loadB = [&](int k0) {
        #pragma unroll
        for (int ntp = 0; ntp < 4; ntp++)
            #pragma unroll
            for (int ks = 0; ks < 2; ks++) {
                uint32_t t4[4];
                ldsm4(t4, sB + ((b_n + ntp * 16) * QK_LDS + k0 + ks * 16 + b_kof) * 2);
                bF[ntp * 2 + 0][ks][0] = t4[0]; bF[ntp * 2 + 0][ks][1] = t4[1];
                bF[ntp * 2 + 1][ks][0] = t4[2]; bF[ntp * 2 + 1][ks][1] = t4[3];
            }
    };
    auto mma_all = [&]() {
        #pragma unroll
        for (int ks = 0; ks < 2; ks++)
            #pragma unroll
            for (int mt = 0; mt < 2; mt++)
                #pragma unroll
                for (int nt = 0; nt < 8; nt++)
                    mma_f16(acc[mt][nt], aF[mt][ks], bF[nt][ks]);
    };

    #pragma unroll
    for (int kg = 0; kg < 2; kg++) {
        const int k0 = kg * 32;
        loadA(k0);
        loadB(k0);
        mma_all();
    }

    #pragma unroll
    for (int mt = 0; mt < 2; mt++) {
        #pragma unroll
        for (int nt = 0; nt < 8; nt++) {
            const int row = bm + wm * 32 + mt * 16 + (lane >> 2);
            const int col = bn + wn * 64 + nt * 8 + ((lane & 3) << 1);
            if (col < SE) {
                const size_t base = (size_t)(bh * Sc + row) * SE + col;
                *(float2*)(AW + base)             = make_float2(acc[mt][nt][0], acc[mt][nt][1]);
                *(float2*)(AW + base + 8ull * SE) = make_float2(acc[mt][nt][2], acc[mt][nt][3]);
            }
        }
    }
}

// ---------------------------------------------------------------------------
// Per-head V^T build (hi only)
// ---------------------------------------------------------------------------
__global__ void vt_build()
{
    __shared__ __half th[32][33];
    const int jt = blockIdx.x, dt = blockIdx.y, bh = blockIdx.z;
    const int b = bh >> 4, h = bh & 15;
    const int j0 = jt * 32, d0 = dt * 32;
    const int tx = threadIdx.x, ty = threadIdx.y;

    #pragma unroll
    for (int k = 0; k < 4; k++) {
        const int j = j0 + ty + k * 8;
        const int d = d0 + tx;
        __half vh;
        if (j < Sc) {
            vh = g_qkvh[(size_t)(b * Sc + j) * E3 + 2 * Ec + h * HDc + d];
        } else if (j < Sc + NEc) {
            vh = g_peh[(size_t)(j - Sc) * HDc + d];
        } else {
            vh = __float2half_rn(0.f);
        }
        th[ty + k * 8][tx] = vh;
    }
    __syncthreads();
    #pragma unroll
    for (int k = 0; k < 4; k++) {
        const int d = d0 + ty + k * 8;
        const int j = j0 + tx;
        g_vth[(size_t)bh * HDc * SE + (size_t)d * SE + j] = th[tx][ty + k * 8];
    }
}

// ---------------------------------------------------------------------------
// AV GEMM (HMMA, single-pass): A = aw hi, B = vt hi. 3-stage pipeline, BK=32.
// ---------------------------------------------------------------------------
constexpr int LDSp  = 40;
constexpr int AV_AT = 128 * LDSp * 2;          // 10240
constexpr int AV_BT = 64 * LDSp * 2;           // 5120
constexpr int AV_ST = AV_AT + AV_BT;           // 15360
constexpr int AV_SMEM = 3 * AV_ST;             // 46080

__global__ void __launch_bounds__(256)
av_mma()
{
    extern __shared__ char sm[];
    const uint32_t sbase = smem_u32(sm);
    const int tid = threadIdx.x;
    const int wid = tid >> 5, lane = tid & 31;
    const int bm = blockIdx.x * 128;
    const int bh = blockIdx.y, b = bh >> 4, h = bh & 15;
    const int nk = SE / 32;   // 21

    auto load_chunk = [&](int kc) {
        if (kc < nk) {
            const uint32_t base = sbase + (kc % 3) * AV_ST;
            const int k0 = kc * 32;
            const int sg = (tid & 3) << 3;
            #pragma unroll
            for (int it = 0; it < 2; it++) {
                const int r = (tid >> 2) + it * 64;
                cpasync16(base + r * 80 + sg * 2,
                          g_awh + (size_t)(bh * Sc + bm + r) * SE + k0 + sg);
            }
            {
                const int r = tid >> 2;
                if (r < 64) {
                    cpasync16(base + AV_AT + r * 80 + sg * 2,
                              g_vth + (size_t)bh * HDc * SE + (size_t)r * SE + k0 + sg);
                }
            }
        }
        CP_COMMIT();
    };

    float acc[8][4];
    #pragma unroll
    for (int nt = 0; nt < 8; nt++)
        #pragma unroll
        for (int i = 0; i < 4; i++) acc[nt][i] = 0.f;

    uint32_t aF[2][4], bF[8][2][2];
    const int a_row = wid * 16 + (lane & 15);
    const int a_kof = (lane >> 4) << 3;
    const int b_n   = (lane & 7) + ((lane & 16) >> 1);
    const int b_kof = ((lane >> 3) & 1) << 3;

    auto loadA = [&](uint32_t tb) {
        #pragma unroll
        for (int ks = 0; ks < 2; ks++)
            ldsm4(aF[ks], tb + (a_row * 80) + (ks * 16 + a_kof) * 2);
    };
    auto loadB = [&](uint32_t tb) {
        #pragma unroll
        for (int ntp = 0; ntp < 4; ntp++)
            #pragma unroll
            for (int ks = 0; ks < 2; ks++) {
                uint32_t t4[4];
                ldsm4(t4, tb + (b_n + ntp * 16) * 80 + (ks * 16 + b_kof) * 2);
                bF[ntp * 2 + 0][ks][0] = t4[0]; bF[ntp * 2 + 0][ks][1] = t4[1];
                bF[ntp * 2 + 1][ks][0] = t4[2]; bF[ntp * 2 + 1][ks][1] = t4[3];
            }
    };
    auto mma_all = [&]() {
        #pragma unroll
        for (int ks = 0; ks < 2; ks++)
            #pragma unroll
            for (int nt = 0; nt < 8; nt++)
                mma_f16(acc[nt], aF[ks], bF[nt][ks]);
    };

    load_chunk(0);
    load_chunk(1);
    for (int kc = 0; kc < nk; kc++) {
        CP_WAIT(1);
        __syncthreads();
        load_chunk(kc + 2);
        const uint32_t base = sbase + (kc % 3) * AV_ST;
        loadA(base);
        loadB(base + AV_AT);
        mma_all();
    }

    #pragma unroll
    for (int nt = 0; nt < 8; nt++) {
        const int row = bm + wid * 16 + (lane >> 2);
        const int col = nt * 8 + ((lane & 3) << 1);
        const size_t i0 = (size_t)(b * Sc + row) * Ec + h * HDc + col;
        const size_t i1 = (size_t)(b * Sc + row + 8) * Ec + h * HDc + col;
        *(uint32_t*)(g_ah + i0) = pack2(acc[nt][0], acc[nt][1]);
        *(uint32_t*)(g_ah + i1) = pack2(acc[nt][2], acc[nt][3]);
    }
}

// ---------------------------------------------------------------------------
// Elementwise prep kernels
// ---------------------------------------------------------------------------
__global__ void __launch_bounds__(256) round_act(
    const float* __restrict__ A, __half* __restrict__ hi, int n2)
{
    const int i = blockIdx.x * 256 + threadIdx.x;
    if (i >= n2) return;
    const float2 v = ((const float2*)A)[i];
    ((uint32_t*)hi)[i] = pack2(v.x, v.y);
}

__device__ __forceinline__ void tr_tile(
    const float* __restrict__ W, int N, __half* __restrict__ dst,
    int rowOff, int ldo, int idx, int xTiles, int tx, int ty)
{
    __shared__ float t[32][33];
    const int n0 = (idx % xTiles) * 32;
    const int k0 = (idx / xTiles) * 32;
    #pragma unroll
    for (int j = 0; j < 32; j += 8)
        t[ty + j][tx] = W[(size_t)(k0 + ty + j) * N + n0 + tx];
    __syncthreads();
    #pragma unroll
    for (int j = 0; j < 32; j += 8)
        dst[(size_t)(rowOff + n0 + ty + j) * ldo + k0 + tx] = __float2half_rn(t[tx][ty + j]);
}

__global__ void __launch_bounds__(256) prep_weights(
    const float* __restrict__ wq, const float* __restrict__ wk,
    const float* __restrict__ wv, const float* __restrict__ wo,
    const float* __restrict__ ff1, const float* __restrict__ ff2,
    const float* __restrict__ pos_emb)
{
    const int bidx = blockIdx.x;
    const int tid = threadIdx.x;
    const int tx = tid & 31, ty = tid >> 5;
    if (bidx < 1024)       tr_tile(wq,  Ec,  g_W3h, 0,      Ec,  bidx,         32,  tx, ty);
    else if (bidx < 2048)  tr_tile(wk,  Ec,  g_W3h, Ec,     Ec,  bidx - 1024,  32,  tx, ty);
    else if (bidx < 3072)  tr_tile(wv,  Ec,  g_W3h, 2 * Ec, Ec,  bidx - 2048,  32,  tx, ty);
    else if (bidx < 4096)  tr_tile(wo,  Ec,  g_Woh, 0,      Ec,  bidx - 3072,  32,  tx, ty);
    else if (bidx < 8192)  tr_tile(ff1, FFc, g_W1h, 0,      Ec,  bidx - 4096,  128, tx, ty);
    else if (bidx < 12288) tr_tile(ff2, Ec,  g_W2h, 0,      FFc, bidx - 8192,  32,  tx, ty);
    else {
        const int i = (bidx - 12288) * 256 + tid;
        if (i < 256 * HDc) {
            const int e = i >> 6;
            g_peh[i] = __float2half_rn((e < NEc) ? pos_emb[i] : 0.f);
        }
    }
}

__global__ void concat_bias(const float* a, const float* b, const float* c) {
    const int i = blockIdx.x * 256 + threadIdx.x;
    if (i < Ec) g_b3[i] = a[i];
    else if (i < 2 * Ec) g_b3[i] = b[i - Ec];
    else if (i < 3 * Ec) g_b3[i] = c[i - 2 * Ec];
}

// ---------------------------------------------------------------------------
// Softmax, warp-per-row: 8 rows per 256-thread block; scores in registers;
// shuffle reductions only; per-row private bucket; emits fp16 aw_ext (hi).
// grid (Sc/8, Hc, Bc)
// ---------------------------------------------------------------------------
__global__ void __launch_bounds__(256) softmax_kernel(
    const float* __restrict__ dist, const int* __restrict__ dt)
{
    __shared__ int dts[Sc];
    __shared__ float bucket[8][NEc + 1];

    const int rg = blockIdx.x, h = blockIdx.y, b = blockIdx.z;
    const int tid = threadIdx.x;
    const int w = tid >> 5, lane = tid & 31;
    const int i = rg * 8 + w;
    const int bh = b * Hc + h;
    const size_t rowbase = (size_t)(bh * Sc + i) * SE;
    const float* drow = dist + ((size_t)b * Sc + i) * Sc;
    float* buck = bucket[w];

    for (int t = tid; t < Sc; t += 256) dts[t] = dt[b * Sc + t];
    for (int t = lane; t < NEc; t += 32) buck[t] = 0.f;
    __syncthreads();

    const int dti = dts[i];

    float s[16];
    int e[16];
    float lmax = -1e30f;
    #pragma unroll
    for (int t = 0; t < 16; t++) {
        const int j = lane + t * 32;
        int rel = dts[j] - dti;
        rel = rel < -64 ? -64 : (rel > 64 ? 64 : rel);
        e[t] = rel + 64;
        const float v = (g_aw[rowbase + j] + g_aw[rowbase + Sc + e[t]]) * 0.125f
                        + 0.6f * drow[j];
        s[t] = v;
        lmax = fmaxf(lmax, v);
    }
    #pragma unroll
    for (int o = 16; o; o >>= 1) lmax = fmaxf(lmax, __shfl_xor_sync(0xffffffffu, lmax, o));

    float lsum = 0.f;
    #pragma unroll
    for (int t = 0; t < 16; t++) {
        s[t] = __expf(s[t] - lmax);
        lsum += s[t];
    }
    #pragma unroll
    for (int o = 16; o; o >>= 1) lsum += __shfl_xor_sync(0xffffffffu, lsum, o);
    const float inv = 1.f / lsum;

    #pragma unroll
    for (int t = 0; t < 16; t++) {
        const float a = s[t] * inv;
        g_awh[rowbase + lane + t * 32] = __float2half_rn(a);
        atomicAdd(&buck[e[t]], a);
    }
    __syncwarp();
    for (int t = lane; t < SE - Sc; t += 32) {
        g_awh[rowbase + Sc + t] = __float2half_rn((t < NEc) ? buck[t] : 0.f);
    }
}

// ---------------------------------------------------------------------------
// out = LayerNorm(X + R); optional fp16 (hi-only) emission.
// ---------------------------------------------------------------------------
template<int EMIT>
__global__ void __launch_bounds__(256) add_ln_kernel(
    const float* __restrict__ X, const float* __restrict__ Rr,
    const float* __restrict__ gam, const float* __restrict__ bet,
    float* __restrict__ Out, __half* __restrict__ Oh)
{
    __shared__ float sh[Ec];
    __shared__ float red[8];
    const int row = blockIdx.x;
    const int tid = threadIdx.x;
    const float* xr = X + (size_t)row * Ec;
    const float* rr = Rr + (size_t)row * Ec;

    float lsum = 0.f;
    for (int t = tid; t < Ec; t += 256) {
        const float v = xr[t] + rr[t];
        sh[t] = v;
        lsum += v;
    }
    #pragma unroll
    for (int o = 16; o; o >>= 1) lsum += __shfl_xor_sync(0xffffffffu, lsum, o);
    if ((tid & 31) == 0) red[tid >> 5] = lsum;
    __syncthreads();
    float tot = 0.f;
    #pragma unroll
    for (int w = 0; w < 8; w++) tot += red[w];
    const float mu = tot * (1.f / Ec);
    __syncthreads();

    float lvar = 0.f;
    for (int t = tid; t < Ec; t += 256) {
        const float d = sh[t] - mu;
        lvar += d * d;
    }
    #pragma unroll
    for (int o = 16; o; o >>= 1) lvar += __shfl_xor_sync(0xffffffffu, lvar, o);
    if ((tid & 31) == 0) red[tid >> 5] = lvar;
    __syncthreads();
    float vtot = 0.f;
    #pragma unroll
    for (int w = 0; w < 8; w++) vtot += red[w];
    const float inv = rsqrtf(vtot * (1.f / Ec) + 1e-5f);

    float* orow = Out + (size_t)row * Ec;
    for (int t = tid; t < Ec; t += 256) {
        const float v = (sh[t] - mu) * inv * gam[t] + bet[t];
        orow[t] = v;
        if (EMIT) Oh[(size_t)row * Ec + t] = __float2half_rn(v);
    }
}

// ---------------------------------------------------------------------------
extern "C" void kernel_launch(void* const* d_in, const int* in_sizes, int n_in,
                              void* d_out, int out_size)
{
    (void)in_sizes; (void)n_in; (void)out_size;
    const float* x       = (const float*)d_in[0];
    const float* dist    = (const float*)d_in[1];
    const int*   dt      = (const int*)d_in[2];
    const float* pos_emb = (const float*)d_in[3];
    const float* wq_w = (const float*)d_in[4];
    const float* wq_b = (const float*)d_in[5];
    const float* wk_w = (const float*)d_in[6];
    const float* wk_b = (const float*)d_in[7];
    const float* wv_w = (const float*)d_in[8];
    const float* wv_b = (const float*)d_in[9];
    const float* wo_w = (const float*)d_in[10];
    const float* wo_b = (const float*)d_in[11];
    const float* ff1_w = (const float*)d_in[12];
    const float* ff1_b = (const float*)d_in[13];
    const float* ff2_w = (const float*)d_in[14];
    const float* ff2_b = (const float*)d_in[15];
    const float* ln1_g = (const float*)d_in[16];
    const float* ln1_b = (const float*)d_in[17];
    const float* ln2_g = (const float*)d_in[18];
    const float* ln2_b = (const float*)d_in[19];
    float* out = (float*)d_out;

    __half *xh, *W3h, *Woh, *W1h, *W2h;
    __half *qkvh, *ah, *hh, *fh;
    float *b3, *AW, *T0, *Hs;
    cudaGetSymbolAddress((void**)&xh, g_xh);
    cudaGetSymbolAddress((void**)&W3h, g_W3h);
    cudaGetSymbolAddress((void**)&Woh, g_Woh);
    cudaGetSymbolAddress((void**)&W1h, g_W1h);
    cudaGetSymbolAddress((void**)&W2h, g_W2h);
    cudaGetSymbolAddress((void**)&qkvh, g_qkvh);
    cudaGetSymbolAddress((void**)&ah, g_ah);
    cudaGetSymbolAddress((void**)&hh, g_hh);
    cudaGetSymbolAddress((void**)&fh, g_fh);
    cudaGetSymbolAddress((void**)&b3, g_b3);
    cudaGetSymbolAddress((void**)&AW, g_aw);
    cudaGetSymbolAddress((void**)&T0, g_t0);
    cudaGetSymbolAddress((void**)&Hs, g_h);

    cudaFuncSetAttribute(mma_gemm<0, 1>, cudaFuncAttributeMaxDynamicSharedMemorySize, MMA_SMEM);
    cudaFuncSetAttribute(mma_gemm<0, 0>, cudaFuncAttributeMaxDynamicSharedMemorySize, MMA_SMEM);
    cudaFuncSetAttribute(mma_gemm<1, 1>, cudaFuncAttributeMaxDynamicSharedMemorySize, MMA_SMEM);
    cudaFuncSetAttribute(qk_scores, cudaFuncAttributeMaxDynamicSharedMemorySize, QK_SMEM);
    cudaFuncSetAttribute(av_mma, cudaFuncAttributeMaxDynamicSharedMemorySize, AV_SMEM);

    dim3 blk(256);
    dim3 tblk(32, 8);

    // prep
    round_act<<<(Mc * Ec / 2 + 255) / 256, blk>>>(x, xh, Mc * Ec / 2);
    prep_weights<<<12288 + 64, blk>>>(wq_w, wk_w, wv_w, wo_w, ff1_w, ff2_w, pos_emb);
    concat_bias<<<12, blk>>>(wq_b, wk_b, wv_b);

    // fused QKV projection (single-pass, BK=64) -> fp16
    mma_gemm<0, 1><<<dim3(E3 / 128, Mc / 128), blk, MMA_SMEM>>>(
        xh, W3h, b3, nullptr, qkvh, Ec, E3);

    // per-head V^T (+pe^T) staging
    vt_build<<<dim3(SE / 32, 2, 128), tblk>>>();

    // fused scores (single-pass)
    qk_scores<<<dim3(6, 4, 128), blk, QK_SMEM>>>(AW);

    // softmax, warp-per-row
    softmax_kernel<<<dim3(Sc / 8, Hc, Bc), blk>>>(dist, dt);

    // attn = aw_ext @ vt^T (single-pass)
    av_mma<<<dim3(4, 128), blk, AV_SMEM>>>();

    // output projection (single-pass, BK=64)
    mma_gemm<0, 0><<<dim3(Ec / 128, Mc / 128), blk, MMA_SMEM>>>(
        ah, Woh, wo_b, T0, nullptr, Ec, Ec);

    // h = LN(x + attn_out), emit fp16 for FF1
    add_ln_kernel<1><<<Mc, blk>>>(x, T0, ln1_g, ln1_b, Hs, hh);

    // FFN (single-pass both, BK=64)
    mma_gemm<1, 1><<<dim3(FFc / 128, Mc / 128), blk, MMA_SMEM>>>(
        hh, W1h, ff1_b, nullptr, fh, Ec, FFc);
    mma_gemm<0, 0><<<dim3(Ec / 128, Mc / 128), blk, MMA_SMEM>>>(
        fh, W2h, ff2_b, T0, nullptr, FFc, Ec);

    // out = LN(h + ffn)
    add_ln_kernel<0><<<Mc, blk>>>(Hs, T0, ln2_g, ln2_b, out, nullptr);
}

// round 12
// speedup vs baseline: 1.1017x; 1.1017x over previous
#include <cuda_runtime.h>
#include <cuda_fp16.h>
#include <cstdint>
#include <math.h>

// Problem constants
constexpr int Bc  = 8;
constexpr int Sc  = 512;
constexpr int Ec  = 1024;
constexpr int Hc  = 16;
constexpr int HDc = 64;
constexpr int FFc = 4096;
constexpr int NEc = 129;           // 2P+1
constexpr int Mc  = Bc * Sc;       // 4096 rows
constexpr int E3  = 3 * Ec;        // 3072
constexpr int SE  = 672;           // extended score width: 512 + 129 + pad

// ---------------------------------------------------------------------------
// Scratch (device globals; no allocation allowed)
// ---------------------------------------------------------------------------
__device__ __align__(256) __half g_xh[Mc * Ec];
__device__ __align__(256) __half g_W3h[E3 * Ec];
__device__ __align__(256) __half g_Woh[Ec * Ec];
__device__ __align__(256) __half g_W1h[FFc * Ec];
__device__ __align__(256) __half g_W2h[Ec * FFc];
__device__ float g_b3[E3];
__device__ __align__(256) __half g_qkvh[Mc * E3];
__device__ __align__(256) __half g_peh[256 * HDc];
__device__ float g_aw[128 * Sc * SE];                  // fp32 scores
__device__ __align__(256) __half g_awh[128 * Sc * SE];
__device__ __align__(256) __half g_vth[128 * HDc * SE];
__device__ __align__(256) __half g_ah[Mc * Ec];
__device__ float g_t0[Mc * Ec];
__device__ float g_h[Mc * Ec];
__device__ __align__(256) __half g_hh[Mc * Ec];
__device__ __align__(256) __half g_fh[Mc * FFc];

// ---------------------------------------------------------------------------
// PTX helpers
// ---------------------------------------------------------------------------
__device__ __forceinline__ uint32_t smem_u32(const void* p) {
    uint32_t a;
    asm("{ .reg .u64 t; cvta.to.shared.u64 t, %1; cvt.u32.u64 %0, t; }" : "=r"(a) : "l"(p));
    return a;
}
__device__ __forceinline__ void cpasync16(uint32_t dst, const void* src) {
    asm volatile("cp.async.cg.shared.global [%0], [%1], 16;" :: "r"(dst), "l"(src));
}
#define CP_COMMIT()  asm volatile("cp.async.commit_group;" ::: "memory")
#define CP_WAIT(n)   asm volatile("cp.async.wait_group %0;" :: "n"(n) : "memory")

__device__ __forceinline__ void ldsm4(uint32_t* r, uint32_t addr) {
    asm volatile("ldmatrix.sync.aligned.m8n8.x4.shared.b16 {%0,%1,%2,%3}, [%4];"
                 : "=r"(r[0]), "=r"(r[1]), "=r"(r[2]), "=r"(r[3]) : "r"(addr));
}
__device__ __forceinline__ void mma_f16(float* c, const uint32_t* a, const uint32_t* b) {
    asm volatile(
        "mma.sync.aligned.m16n8k16.row.col.f32.f16.f16.f32 "
        "{%0,%1,%2,%3}, {%4,%5,%6,%7}, {%8,%9}, {%0,%1,%2,%3};"
        : "+f"(c[0]), "+f"(c[1]), "+f"(c[2]), "+f"(c[3])
        : "r"(a[0]), "r"(a[1]), "r"(a[2]), "r"(a[3]), "r"(b[0]), "r"(b[1]));
}
__device__ __forceinline__ uint32_t pack2(float v0, float v1) {
    __half2 ph = __halves2half2(__float2half_rn(v0), __float2half_rn(v1));
    return *(uint32_t*)&ph;
}

// ---------------------------------------------------------------------------
// HMMA GEMM (single-pass, BK=32): C[M,N] = Ah[M,K] @ Bh[N,K]^T + bias
// 128x128 CTA tile, 8 warps of 32x64. 4-stage cp.async pipeline (depth 3),
// ONE __syncthreads per chunk.
// ---------------------------------------------------------------------------
constexpr int LDSp  = 40;
constexpr int TILEB = 128 * LDSp * 2;      // 10240
constexpr int BUFB1 = 2 * TILEB;           // A,B = 20480
constexpr int MMA_SMEM = 4 * BUFB1;        // 81920

template<int RELU, int EMITH>
__global__ void __launch_bounds__(256)
mma_gemm(const __half* __restrict__ Ah, const __half* __restrict__ Bh,
         const float* __restrict__ bias, float* __restrict__ C,
         __half* __restrict__ Ch, int K, int N)
{
    extern __shared__ char sm[];
    const uint32_t sbase = smem_u32(sm);
    const int tid = threadIdx.x;
    const int wid = tid >> 5, lane = tid & 31;
    const int wm = wid & 3, wn = wid >> 2;
    const int bm = blockIdx.y * 128, bn = blockIdx.x * 128;
    const int nk = K / 32;

    const int r0l = tid >> 2, sg = (tid & 3) << 3;

    auto load_chunk = [&](int kc) {
        if (kc < nk) {
            const uint32_t base = sbase + (kc & 3) * BUFB1;
            const int k0 = kc * 32;
            #pragma unroll
            for (int it = 0; it < 2; it++) {
                const int r = r0l + it * 64;
                const uint32_t dst = base + r * 80 + sg * 2;
                cpasync16(dst,         Ah + (size_t)(bm + r) * K + k0 + sg);
                cpasync16(dst + TILEB, Bh + (size_t)(bn + r) * K + k0 + sg);
            }
        }
        CP_COMMIT();
    };

    float acc[2][8][4];
    #pragma unroll
    for (int mt = 0; mt < 2; mt++)
        #pragma unroll
        for (int nt = 0; nt < 8; nt++)
            #pragma unroll
            for (int i = 0; i < 4; i++) acc[mt][nt][i] = 0.f;

    uint32_t aF[2][2][4];
    uint32_t bF[8][2][2];

    const int a_row = wm * 32 + (lane & 15);
    const int a_kof = (lane >> 4) << 3;
    const int b_n   = wn * 64 + (lane & 7) + ((lane & 16) >> 1);
    const int b_kof = ((lane >> 3) & 1) << 3;

    auto loadA = [&](uint32_t tbase) {
        #pragma unroll
        for (int mt = 0; mt < 2; mt++)
            #pragma unroll
            for (int ks = 0; ks < 2; ks++)
                ldsm4(aF[mt][ks], tbase + (a_row + mt * 16) * 80 + (ks * 16 + a_kof) * 2);
    };
    auto loadB = [&](uint32_t tbase) {
        #pragma unroll
        for (int ntp = 0; ntp < 4; ntp++)
            #pragma unroll
            for (int ks = 0; ks < 2; ks++) {
                uint32_t t4[4];
                ldsm4(t4, tbase + (b_n + ntp * 16) * 80 + (ks * 16 + b_kof) * 2);
                bF[ntp * 2 + 0][ks][0] = t4[0]; bF[ntp * 2 + 0][ks][1] = t4[1];
                bF[ntp * 2 + 1][ks][0] = t4[2]; bF[ntp * 2 + 1][ks][1] = t4[3];
            }
    };
    auto mma_all = [&]() {
        #pragma unroll
        for (int ks = 0; ks < 2; ks++)
            #pragma unroll
            for (int mt = 0; mt < 2; mt++)
                #pragma unroll
                for (int nt = 0; nt < 8; nt++)
                    mma_f16(acc[mt][nt], aF[mt][ks], bF[nt][ks]);
    };

    load_chunk(0);
    load_chunk(1);
    load_chunk(2);
    for (int kc = 0; kc < nk; kc++) {
        CP_WAIT(2);              // chunk kc complete (2 newer groups outstanding)
        __syncthreads();         // publish; guards stage reuse
        load_chunk(kc + 3);      // prefetch into stage (kc+3)&3 (stage of kc-1)

        const uint32_t base = sbase + (kc & 3) * BUFB1;
        loadA(base);
        loadB(base + TILEB);
        mma_all();
    }

    #pragma unroll
    for (int mt = 0; mt < 2; mt++) {
        #pragma unroll
        for (int nt = 0; nt < 8; nt++) {
            const int row = bm + wm * 32 + mt * 16 + (lane >> 2);
            const int col = bn + wn * 64 + nt * 8 + ((lane & 3) << 1);
            const float bi0 = bias[col], bi1 = bias[col + 1];
            float o00 = acc[mt][nt][0] + bi0, o01 = acc[mt][nt][1] + bi1;
            float o10 = acc[mt][nt][2] + bi0, o11 = acc[mt][nt][3] + bi1;
            if (RELU) {
                o00 = fmaxf(o00, 0.f); o01 = fmaxf(o01, 0.f);
                o10 = fmaxf(o10, 0.f); o11 = fmaxf(o11, 0.f);
            }
            const size_t i0 = (size_t)row * N + col;
            const size_t i1 = (size_t)(row + 8) * N + col;
            if (EMITH) {
                *(uint32_t*)(Ch + i0) = pack2(o00, o01);
                *(uint32_t*)(Ch + i1) = pack2(o10, o11);
            } else {
                *(float2*)(C + i0) = make_float2(o00, o01);
                *(float2*)(C + i1) = make_float2(o10, o11);
            }
        }
    }
}

// ---------------------------------------------------------------------------
// Fused scores GEMM (HMMA, single-pass): per (b,h):
//   AW[i, j]     = Q_h[i,:] . K_h[j,:]       (j < 512)
//   AW[i, 512+e] = Q_h[i,:] . pos_emb[e,:]   (e < 129; pad rows zero)
// ---------------------------------------------------------------------------
constexpr int QK_LDS = 72;
constexpr int QK_T   = 128 * QK_LDS * 2;     // 18432
constexpr int QK_SMEM = 2 * QK_T;            // 36864 B

__global__ void __launch_bounds__(256)
qk_scores(float* __restrict__ AW)
{
    extern __shared__ char sm[];
    const uint32_t sA = smem_u32(sm);
    const uint32_t sB = sA + QK_T;
    const int tid = threadIdx.x;
    const int wid = tid >> 5, lane = tid & 31;
    const int wm = wid & 3, wn = wid >> 2;
    const int bn = blockIdx.x * 128, bm = blockIdx.y * 128;
    const int bh = blockIdx.z, b = bh >> 4, h = bh & 15;

    {
        const int r0 = tid >> 3, sg = (tid & 7) << 3;
        #pragma unroll
        for (int it = 0; it < 4; it++) {
            const int r = r0 + it * 32;
            const uint32_t off = (r * QK_LDS + sg) * 2;
            cpasync16(sA + off, g_qkvh + (size_t)(b * Sc + bm + r) * E3 + h * HDc + sg);
            const int gr = bn + r;
            const __half* bph;
            if (gr < Sc) {
                bph = g_qkvh + (size_t)(b * Sc + gr) * E3 + Ec + h * HDc + sg;
            } else {
                bph = g_peh + (size_t)(gr - Sc) * HDc + sg;
            }
            cpasync16(sB + off, bph);
        }
        CP_COMMIT(); CP_WAIT(0);
        __syncthreads();
    }

    float acc[2][8][4];
    #pragma unroll
    for (int mt = 0; mt < 2; mt++)
        #pragma unroll
        for (int nt = 0; nt < 8; nt++)
            #pragma unroll
            for (int i = 0; i < 4; i++) acc[mt][nt][i] = 0.f;

    uint32_t aF[2][2][4], bF[8][2][2];
    const int a_row = wm * 32 + (lane & 15);
    const int a_kof = (lane >> 4) << 3;
    const int b_n   = wn * 64 + (lane & 7) + ((lane & 16) >> 1);
    const int b_kof = ((lane >> 3) & 1) << 3;

    auto loadA = [&](int k0) {
        #pragma unroll
        for (int mt = 0; mt < 2; mt++)
            #pragma unroll
            for (int ks = 0; ks < 2; ks++)
                ldsm4(aF[mt][ks], sA + ((a_row + mt * 16) * QK_LDS + k0 + ks * 16 + a_kof) * 2);
    };
    auto loadB = [&](int k0) {
        #pragma unroll
        for (int ntp = 0; ntp < 4; ntp++)
            #pragma unroll
            for (int ks = 0; ks < 2; ks++) {
                uint32_t t4[4];
                ldsm4(t4, sB + ((b_n + ntp * 16) * QK_LDS + k0 + ks * 16 + b_kof) * 2);
                bF[ntp * 2 + 0][ks][0] = t4[0]; bF[ntp * 2 + 0][ks][1] = t4[1];
                bF[ntp * 2 + 1][ks][0] = t4[2]; bF[ntp * 2 + 1][ks][1] = t4[3];
            }
    };
    auto mma_all = [&]() {
        #pragma unroll
        for (int ks = 0; ks < 2; ks++)
            #pragma unroll
            for (int mt = 0; mt < 2; mt++)
                #pragma unroll
                for (int nt = 0; nt < 8; nt++)
                    mma_f16(acc[mt][nt], aF[mt][ks], bF[nt][ks]);
    };

    #pragma unroll
    for (int kg = 0; kg < 2; kg++) {
        const int k0 = kg * 32;
        loadA(k0);
        loadB(k0);
        mma_all();
    }

    #pragma unroll
    for (int mt = 0; mt < 2; mt++) {
        #pragma unroll
        for (int nt = 0; nt < 8; nt++) {
            const int row = bm + wm * 32 + mt * 16 + (lane >> 2);
            const int col = bn + wn * 64 + nt * 8 + ((lane & 3) << 1);
            if (col < SE) {
                const size_t base = (size_t)(bh * Sc + row) * SE + col;
                *(float2*)(AW + base)             = make_float2(acc[mt][nt][0], acc[mt][nt][1]);
                *(float2*)(AW + base + 8ull * SE) = make_float2(acc[mt][nt][2], acc[mt][nt][3]);
            }
        }
    }
}

// ---------------------------------------------------------------------------
// Per-head V^T build (hi only)
// ---------------------------------------------------------------------------
__global__ void vt_build()
{
    __shared__ __half th[32][33];
    const int jt = blockIdx.x, dt = blockIdx.y, bh = blockIdx.z;
    const int b = bh >> 4, h = bh & 15;
    const int j0 = jt * 32, d0 = dt * 32;
    const int tx = threadIdx.x, ty = threadIdx.y;

    #pragma unroll
    for (int k = 0; k < 4; k++) {
        const int j = j0 + ty + k * 8;
        const int d = d0 + tx;
        __half vh;
        if (j < Sc) {
            vh = g_qkvh[(size_t)(b * Sc + j) * E3 + 2 * Ec + h * HDc + d];
        } else if (j < Sc + NEc) {
            vh = g_peh[(size_t)(j - Sc) * HDc + d];
        } else {
            vh = __float2half_rn(0.f);
        }
        th[ty + k * 8][tx] = vh;
    }
    __syncthreads();
    #pragma unroll
    for (int k = 0; k < 4; k++) {
        const int d = d0 + ty + k * 8;
        const int j = j0 + tx;
        g_vth[(size_t)bh * HDc * SE + (size_t)d * SE + j] = th[tx][ty + k * 8];
    }
}

// ---------------------------------------------------------------------------
// AV GEMM (HMMA, single-pass): A = aw hi, B = vt hi. 4-stage pipeline, BK=32.
// ---------------------------------------------------------------------------
constexpr int AV_AT = 128 * LDSp * 2;          // 10240
constexpr int AV_BT = 64 * LDSp * 2;           // 5120
constexpr int AV_ST = AV_AT + AV_BT;           // 15360
constexpr int AV_SMEM = 4 * AV_ST;             // 61440

__global__ void __launch_bounds__(256)
av_mma()
{
    extern __shared__ char sm[];
    const uint32_t sbase = smem_u32(sm);
    const int tid = threadIdx.x;
    const int wid = tid >> 5, lane = tid & 31;
    const int bm = blockIdx.x * 128;
    const int bh = blockIdx.y, b = bh >> 4, h = bh & 15;
    const int nk = SE / 32;   // 21

    auto load_chunk = [&](int kc) {
        if (kc < nk) {
            const uint32_t base = sbase + (kc & 3) * AV_ST;
            const int k0 = kc * 32;
            const int sg = (tid & 3) << 3;
            #pragma unroll
            for (int it = 0; it < 2; it++) {
                const int r = (tid >> 2) + it * 64;
                cpasync16(base + r * 80 + sg * 2,
                          g_awh + (size_t)(bh * Sc + bm + r) * SE + k0 + sg);
            }
            {
                const int r = tid >> 2;
                if (r < 64) {
                    cpasync16(base + AV_AT + r * 80 + sg * 2,
                              g_vth + (size_t)bh * HDc * SE + (size_t)r * SE + k0 + sg);
                }
            }
        }
        CP_COMMIT();
    };

    float acc[8][4];
    #pragma unroll
    for (int nt = 0; nt < 8; nt++)
        #pragma unroll
        for (int i = 0; i < 4; i++) acc[nt][i] = 0.f;

    uint32_t aF[2][4], bF[8][2][2];
    const int a_row = wid * 16 + (lane & 15);
    const int a_kof = (lane >> 4) << 3;
    const int b_n   = (lane & 7) + ((lane & 16) >> 1);
    const int b_kof = ((lane >> 3) & 1) << 3;

    auto loadA = [&](uint32_t tb) {
        #pragma unroll
        for (int ks = 0; ks < 2; ks++)
            ldsm4(aF[ks], tb + (a_row * 80) + (ks * 16 + a_kof) * 2);
    };
    auto loadB = [&](uint32_t tb) {
        #pragma unroll
        for (int ntp = 0; ntp < 4; ntp++)
            #pragma unroll
            for (int ks = 0; ks < 2; ks++) {
                uint32_t t4[4];
                ldsm4(t4, tb + (b_n + ntp * 16) * 80 + (ks * 16 + b_kof) * 2);
                bF[ntp * 2 + 0][ks][0] = t4[0]; bF[ntp * 2 + 0][ks][1] = t4[1];
                bF[ntp * 2 + 1][ks][0] = t4[2]; bF[ntp * 2 + 1][ks][1] = t4[3];
            }
    };
    auto mma_all = [&]() {
        #pragma unroll
        for (int ks = 0; ks < 2; ks++)
            #pragma unroll
            for (int nt = 0; nt < 8; nt++)
                mma_f16(acc[nt], aF[ks], bF[nt][ks]);
    };

    load_chunk(0);
    load_chunk(1);
    load_chunk(2);
    for (int kc = 0; kc < nk; kc++) {
        CP_WAIT(2);
        __syncthreads();
        load_chunk(kc + 3);
        const uint32_t base = sbase + (kc & 3) * AV_ST;
        loadA(base);
        loadB(base + AV_AT);
        mma_all();
    }

    #pragma unroll
    for (int nt = 0; nt < 8; nt++) {
        const int row = bm + wid * 16 + (lane >> 2);
        const int col = nt * 8 + ((lane & 3) << 1);
        const size_t i0 = (size_t)(b * Sc + row) * Ec + h * HDc + col;
        const size_t i1 = (size_t)(b * Sc + row + 8) * Ec + h * HDc + col;
        *(uint32_t*)(g_ah + i0) = pack2(acc[nt][0], acc[nt][1]);
        *(uint32_t*)(g_ah + i1) = pack2(acc[nt][2], acc[nt][3]);
    }
}

// ---------------------------------------------------------------------------
// Elementwise prep kernels
// ---------------------------------------------------------------------------
__global__ void __launch_bounds__(256) round_act(
    const float* __restrict__ A, __half* __restrict__ hi, int n2)
{
    const int i = blockIdx.x * 256 + threadIdx.x;
    if (i >= n2) return;
    const float2 v = ((const float2*)A)[i];
    ((uint32_t*)hi)[i] = pack2(v.x, v.y);
}

__device__ __forceinline__ void tr_tile(
    const float* __restrict__ W, int N, __half* __restrict__ dst,
    int rowOff, int ldo, int idx, int xTiles, int tx, int ty)
{
    __shared__ float t[32][33];
    const int n0 = (idx % xTiles) * 32;
    const int k0 = (idx / xTiles) * 32;
    #pragma unroll
    for (int j = 0; j < 32; j += 8)
        t[ty + j][tx] = W[(size_t)(k0 + ty + j) * N + n0 + tx];
    __syncthreads();
    #pragma unroll
    for (int j = 0; j < 32; j += 8)
        dst[(size_t)(rowOff + n0 + ty + j) * ldo + k0 + tx] = __float2half_rn(t[tx][ty + j]);
}

__global__ void __launch_bounds__(256) prep_weights(
    const float* __restrict__ wq, const float* __restrict__ wk,
    const float* __restrict__ wv, const float* __restrict__ wo,
    const float* __restrict__ ff1, const float* __restrict__ ff2,
    const float* __restrict__ pos_emb)
{
    const int bidx = blockIdx.x;
    const int tid = threadIdx.x;
    const int tx = tid & 31, ty = tid >> 5;
    if (bidx < 1024)       tr_tile(wq,  Ec,  g_W3h, 0,      Ec,  bidx,         32,  tx, ty);
    else if (bidx < 2048)  tr_tile(wk,  Ec,  g_W3h, Ec,     Ec,  bidx - 1024,  32,  tx, ty);
    else if (bidx < 3072)  tr_tile(wv,  Ec,  g_W3h, 2 * Ec, Ec,  bidx - 2048,  32,  tx, ty);
    else if (bidx < 4096)  tr_tile(wo,  Ec,  g_Woh, 0,      Ec,  bidx - 3072,  32,  tx, ty);
    else if (bidx < 8192)  tr_tile(ff1, FFc, g_W1h, 0,      Ec,  bidx - 4096,  128, tx, ty);
    else if (bidx < 12288) tr_tile(ff2, Ec,  g_W2h, 0,      FFc, bidx - 8192,  32,  tx, ty);
    else {
        const int i = (bidx - 12288) * 256 + tid;
        if (i < 256 * HDc) {
            const int e = i >> 6;
            g_peh[i] = __float2half_rn((e < NEc) ? pos_emb[i] : 0.f);
        }
    }
}

__global__ void concat_bias(const float* a, const float* b, const float* c) {
    const int i = blockIdx.x * 256 + threadIdx.x;
    if (i < Ec) g_b3[i] = a[i];
    else if (i < 2 * Ec) g_b3[i] = b[i - Ec];
    else if (i < 3 * Ec) g_b3[i] = c[i - 2 * Ec];
}

// ---------------------------------------------------------------------------
// Softmax, warp-per-row
// ---------------------------------------------------------------------------
__global__ void __launch_bounds__(256) softmax_kernel(
    const float* __restrict__ dist, const int* __restrict__ dt)
{
    __shared__ int dts[Sc];
    __shared__ float bucket[8][NEc + 1];

    const int rg = blockIdx.x, h = blockIdx.y, b = blockIdx.z;
    const int tid = threadIdx.x;
    const int w = tid >> 5, lane = tid & 31;
    const int i = rg * 8 + w;
    const int bh = b * Hc + h;
    const size_t rowbase = (size_t)(bh * Sc + i) * SE;
    const float* drow = dist + ((size_t)b * Sc + i) * Sc;
    float* buck = bucket[w];

    for (int t = tid; t < Sc; t += 256) dts[t] = dt[b * Sc + t];
    for (int t = lane; t < NEc; t += 32) buck[t] = 0.f;
    __syncthreads();

    const int dti = dts[i];

    float s[16];
    int e[16];
    float lmax = -1e30f;
    #pragma unroll
    for (int t = 0; t < 16; t++) {
        const int j = lane + t * 32;
        int rel = dts[j] - dti;
        rel = rel < -64 ? -64 : (rel > 64 ? 64 : rel);
        e[t] = rel + 64;
        const float v = (g_aw[rowbase + j] + g_aw[rowbase + Sc + e[t]]) * 0.125f
                        + 0.6f * drow[j];
        s[t] = v;
        lmax = fmaxf(lmax, v);
    }
    #pragma unroll
    for (int o = 16; o; o >>= 1) lmax = fmaxf(lmax, __shfl_xor_sync(0xffffffffu, lmax, o));

    float lsum = 0.f;
    #pragma unroll
    for (int t = 0; t < 16; t++) {
        s[t] = __expf(s[t] - lmax);
        lsum += s[t];
    }
    #pragma unroll
    for (int o = 16; o; o >>= 1) lsum += __shfl_xor_sync(0xffffffffu, lsum, o);
    const float inv = 1.f / lsum;

    #pragma unroll
    for (int t = 0; t < 16; t++) {
        const float a = s[t] * inv;
        g_awh[rowbase + lane + t * 32] = __float2half_rn(a);
        atomicAdd(&buck[e[t]], a);
    }
    __syncwarp();
    for (int t = lane; t < SE - Sc; t += 32) {
        g_awh[rowbase + Sc + t] = __float2half_rn((t < NEc) ? buck[t] : 0.f);
    }
}

// ---------------------------------------------------------------------------
// out = LayerNorm(X + R); optional fp16 (hi-only) emission.
// ---------------------------------------------------------------------------
template<int EMIT>
__global__ void __launch_bounds__(256) add_ln_kernel(
    const float* __restrict__ X, const float* __restrict__ Rr,
    const float* __restrict__ gam, const float* __restrict__ bet,
    float* __restrict__ Out, __half* __restrict__ Oh)
{
    __shared__ float sh[Ec];
    __shared__ float red[8];
    const int row = blockIdx.x;
    const int tid = threadIdx.x;
    const float* xr = X + (size_t)row * Ec;
    const float* rr = Rr + (size_t)row * Ec;

    float lsum = 0.f;
    for (int t = tid; t < Ec; t += 256) {
        const float v = xr[t] + rr[t];
        sh[t] = v;
        lsum += v;
    }
    #pragma unroll
    for (int o = 16; o; o >>= 1) lsum += __shfl_xor_sync(0xffffffffu, lsum, o);
    if ((tid & 31) == 0) red[tid >> 5] = lsum;
    __syncthreads();
    float tot = 0.f;
    #pragma unroll
    for (int w = 0; w < 8; w++) tot += red[w];
    const float mu = tot * (1.f / Ec);
    __syncthreads();

    float lvar = 0.f;
    for (int t = tid; t < Ec; t += 256) {
        const float d = sh[t] - mu;
        lvar += d * d;
    }
    #pragma unroll
    for (int o = 16; o; o >>= 1) lvar += __shfl_xor_sync(0xffffffffu, lvar, o);
    if ((tid & 31) == 0) red[tid >> 5] = lvar;
    __syncthreads();
    float vtot = 0.f;
    #pragma unroll
    for (int w = 0; w < 8; w++) vtot += red[w];
    const float inv = rsqrtf(vtot * (1.f / Ec) + 1e-5f);

    float* orow = Out + (size_t)row * Ec;
    for (int t = tid; t < Ec; t += 256) {
        const float v = (sh[t] - mu) * inv * gam[t] + bet[t];
        orow[t] = v;
        if (EMIT) Oh[(size_t)row * Ec + t] = __float2half_rn(v);
    }
}

// ---------------------------------------------------------------------------
extern "C" void kernel_launch(void* const* d_in, const int* in_sizes, int n_in,
                              void* d_out, int out_size)
{
    (void)in_sizes; (void)n_in; (void)out_size;
    const float* x       = (const float*)d_in[0];
    const float* dist    = (const float*)d_in[1];
    const int*   dt      = (const int*)d_in[2];
    const float* pos_emb = (const float*)d_in[3];
    const float* wq_w = (const float*)d_in[4];
    const float* wq_b = (const float*)d_in[5];
    const float* wk_w = (const float*)d_in[6];
    const float* wk_b = (const float*)d_in[7];
    const float* wv_w = (const float*)d_in[8];
    const float* wv_b = (const float*)d_in[9];
    const float* wo_w = (const float*)d_in[10];
    const float* wo_b = (const float*)d_in[11];
    const float* ff1_w = (const float*)d_in[12];
    const float* ff1_b = (const float*)d_in[13];
    const float* ff2_w = (const float*)d_in[14];
    const float* ff2_b = (const float*)d_in[15];
    const float* ln1_g = (const float*)d_in[16];
    const float* ln1_b = (const float*)d_in[17];
    const float* ln2_g = (const float*)d_in[18];
    const float* ln2_b = (const float*)d_in[19];
    float* out = (float*)d_out;

    __half *xh, *W3h, *Woh, *W1h, *W2h;
    __half *qkvh, *ah, *hh, *fh;
    float *b3, *AW, *T0, *Hs;
    cudaGetSymbolAddress((void**)&xh, g_xh);
    cudaGetSymbolAddress((void**)&W3h, g_W3h);
    cudaGetSymbolAddress((void**)&Woh, g_Woh);
    cudaGetSymbolAddress((void**)&W1h, g_W1h);
    cudaGetSymbolAddress((void**)&W2h, g_W2h);
    cudaGetSymbolAddress((void**)&qkvh, g_qkvh);
    cudaGetSymbolAddress((void**)&ah, g_ah);
    cudaGetSymbolAddress((void**)&hh, g_hh);
    cudaGetSymbolAddress((void**)&fh, g_fh);
    cudaGetSymbolAddress((void**)&b3, g_b3);
    cudaGetSymbolAddress((void**)&AW, g_aw);
    cudaGetSymbolAddress((void**)&T0, g_t0);
    cudaGetSymbolAddress((void**)&Hs, g_h);

    cudaFuncSetAttribute(mma_gemm<0, 1>, cudaFuncAttributeMaxDynamicSharedMemorySize, MMA_SMEM);
    cudaFuncSetAttribute(mma_gemm<0, 0>, cudaFuncAttributeMaxDynamicSharedMemorySize, MMA_SMEM);
    cudaFuncSetAttribute(mma_gemm<1, 1>, cudaFuncAttributeMaxDynamicSharedMemorySize, MMA_SMEM);
    cudaFuncSetAttribute(qk_scores, cudaFuncAttributeMaxDynamicSharedMemorySize, QK_SMEM);
    cudaFuncSetAttribute(av_mma, cudaFuncAttributeMaxDynamicSharedMemorySize, AV_SMEM);

    dim3 blk(256);
    dim3 tblk(32, 8);

    // prep
    round_act<<<(Mc * Ec / 2 + 255) / 256, blk>>>(x, xh, Mc * Ec / 2);
    prep_weights<<<12288 + 64, blk>>>(wq_w, wk_w, wv_w, wo_w, ff1_w, ff2_w, pos_emb);
    concat_bias<<<12, blk>>>(wq_b, wk_b, wv_b);

    // fused QKV projection (single-pass, BK=32, 4-stage)
    mma_gemm<0, 1><<<dim3(E3 / 128, Mc / 128), blk, MMA_SMEM>>>(
        xh, W3h, b3, nullptr, qkvh, Ec, E3);

    // per-head V^T (+pe^T) staging
    vt_build<<<dim3(SE / 32, 2, 128), tblk>>>();

    // fused scores (single-pass)
    qk_scores<<<dim3(6, 4, 128), blk, QK_SMEM>>>(AW);

    // softmax, warp-per-row
    softmax_kernel<<<dim3(Sc / 8, Hc, Bc), blk>>>(dist, dt);

    // attn = aw_ext @ vt^T (single-pass, 4-stage)
    av_mma<<<dim3(4, 128), blk, AV_SMEM>>>();

    // output projection
    mma_gemm<0, 0><<<dim3(Ec / 128, Mc / 128), blk, MMA_SMEM>>>(
        ah, Woh, wo_b, T0, nullptr, Ec, Ec);

    // h = LN(x + attn_out), emit fp16 for FF1
    add_ln_kernel<1><<<Mc, blk>>>(x, T0, ln1_g, ln1_b, Hs, hh);

    // FFN (single-pass both)
    mma_gemm<1, 1><<<dim3(FFc / 128, Mc / 128), blk, MMA_SMEM>>>(
        hh, W1h, ff1_b, nullptr, fh, Ec, FFc);
    mma_gemm<0, 0><<<dim3(Ec / 128, Mc / 128), blk, MMA_SMEM>>>(
        fh, W2h, ff2_b, T0, nullptr, FFc, Ec);

    // out = LN(h + ffn)
    add_ln_kernel<0><<<Mc, blk>>>(Hs, T0, ln2_g, ln2_b, out, nullptr);
}

// round 13
// speedup vs baseline: 1.1180x; 1.0148x over previous
#include <cuda_runtime.h>
#include <cuda_fp16.h>
#include <cstdint>
#include <math.h>

// Problem constants
constexpr int Bc  = 8;
constexpr int Sc  = 512;
constexpr int Ec  = 1024;
constexpr int Hc  = 16;
constexpr int HDc = 64;
constexpr int FFc = 4096;
constexpr int NEc = 129;           // 2P+1
constexpr int Mc  = Bc * Sc;       // 4096 rows
constexpr int E3  = 3 * Ec;        // 3072
constexpr int SE  = 672;           // extended score width: 512 + 129 + pad

// ---------------------------------------------------------------------------
// Scratch (device globals; no allocation allowed)
// ---------------------------------------------------------------------------
__device__ __align__(256) __half g_xh[Mc * Ec];
__device__ __align__(256) __half g_W3h[E3 * Ec];
__device__ __align__(256) __half g_Woh[Ec * Ec];
__device__ __align__(256) __half g_W1h[FFc * Ec];
__device__ __align__(256) __half g_W2h[Ec * FFc];
__device__ float g_b3[E3];
__device__ __align__(256) __half g_qkvh[Mc * E3];
__device__ __align__(256) __half g_peh[256 * HDc];
__device__ __align__(256) __half g_aws[128 * Sc * SE];  // fp16 raw scores (88 MB)
__device__ __align__(256) __half g_awh[128 * Sc * SE];  // fp16 softmax weights
__device__ __align__(256) __half g_vth[128 * HDc * SE];
__device__ __align__(256) __half g_ah[Mc * Ec];
__device__ float g_t0[Mc * Ec];
__device__ float g_h[Mc * Ec];
__device__ __align__(256) __half g_hh[Mc * Ec];
__device__ __align__(256) __half g_fh[Mc * FFc];

// ---------------------------------------------------------------------------
// PTX helpers
// ---------------------------------------------------------------------------
__device__ __forceinline__ uint32_t smem_u32(const void* p) {
    uint32_t a;
    asm("{ .reg .u64 t; cvta.to.shared.u64 t, %1; cvt.u32.u64 %0, t; }" : "=r"(a) : "l"(p));
    return a;
}
__device__ __forceinline__ void cpasync16(uint32_t dst, const void* src) {
    asm volatile("cp.async.cg.shared.global [%0], [%1], 16;" :: "r"(dst), "l"(src));
}
#define CP_COMMIT()  asm volatile("cp.async.commit_group;" ::: "memory")
#define CP_WAIT(n)   asm volatile("cp.async.wait_group %0;" :: "n"(n) : "memory")

__device__ __forceinline__ void ldsm4(uint32_t* r, uint32_t addr) {
    asm volatile("ldmatrix.sync.aligned.m8n8.x4.shared.b16 {%0,%1,%2,%3}, [%4];"
                 : "=r"(r[0]), "=r"(r[1]), "=r"(r[2]), "=r"(r[3]) : "r"(addr));
}
__device__ __forceinline__ void mma_f16(float* c, const uint32_t* a, const uint32_t* b) {
    asm volatile(
        "mma.sync.aligned.m16n8k16.row.col.f32.f16.f16.f32 "
        "{%0,%1,%2,%3}, {%4,%5,%6,%7}, {%8,%9}, {%0,%1,%2,%3};"
        : "+f"(c[0]), "+f"(c[1]), "+f"(c[2]), "+f"(c[3])
        : "r"(a[0]), "r"(a[1]), "r"(a[2]), "r"(a[3]), "r"(b[0]), "r"(b[1]));
}
__device__ __forceinline__ uint32_t pack2(float v0, float v1) {
    __half2 ph = __halves2half2(__float2half_rn(v0), __float2half_rn(v1));
    return *(uint32_t*)&ph;
}

// ---------------------------------------------------------------------------
// HMMA GEMM (single-pass, BK=32): C[M,N] = Ah[M,K] @ Bh[N,K]^T + bias
// 128x128 CTA tile, 8 warps of 32x64. 3-stage cp.async pipeline,
// ONE __syncthreads per chunk.
// ---------------------------------------------------------------------------
constexpr int LDSp  = 40;
constexpr int TILEB = 128 * LDSp * 2;      // 10240
constexpr int BUFB1 = 2 * TILEB;           // A,B = 20480
constexpr int MMA_SMEM = 3 * BUFB1;        // 61440

template<int RELU, int EMITH>
__global__ void __launch_bounds__(256)
mma_gemm(const __half* __restrict__ Ah, const __half* __restrict__ Bh,
         const float* __restrict__ bias, float* __restrict__ C,
         __half* __restrict__ Ch, int K, int N)
{
    extern __shared__ char sm[];
    const uint32_t sbase = smem_u32(sm);
    const int tid = threadIdx.x;
    const int wid = tid >> 5, lane = tid & 31;
    const int wm = wid & 3, wn = wid >> 2;
    const int bm = blockIdx.y * 128, bn = blockIdx.x * 128;
    const int nk = K / 32;

    const int r0l = tid >> 2, sg = (tid & 3) << 3;

    auto load_chunk = [&](int kc) {
        if (kc < nk) {
            const uint32_t base = sbase + (kc % 3) * BUFB1;
            const int k0 = kc * 32;
            #pragma unroll
            for (int it = 0; it < 2; it++) {
                const int r = r0l + it * 64;
                const uint32_t dst = base + r * 80 + sg * 2;
                cpasync16(dst,         Ah + (size_t)(bm + r) * K + k0 + sg);
                cpasync16(dst + TILEB, Bh + (size_t)(bn + r) * K + k0 + sg);
            }
        }
        CP_COMMIT();
    };

    float acc[2][8][4];
    #pragma unroll
    for (int mt = 0; mt < 2; mt++)
        #pragma unroll
        for (int nt = 0; nt < 8; nt++)
            #pragma unroll
            for (int i = 0; i < 4; i++) acc[mt][nt][i] = 0.f;

    uint32_t aF[2][2][4];
    uint32_t bF[8][2][2];

    const int a_row = wm * 32 + (lane & 15);
    const int a_kof = (lane >> 4) << 3;
    const int b_n   = wn * 64 + (lane & 7) + ((lane & 16) >> 1);
    const int b_kof = ((lane >> 3) & 1) << 3;

    auto loadA = [&](uint32_t tbase) {
        #pragma unroll
        for (int mt = 0; mt < 2; mt++)
            #pragma unroll
            for (int ks = 0; ks < 2; ks++)
                ldsm4(aF[mt][ks], tbase + (a_row + mt * 16) * 80 + (ks * 16 + a_kof) * 2);
    };
    auto loadB = [&](uint32_t tbase) {
        #pragma unroll
        for (int ntp = 0; ntp < 4; ntp++)
            #pragma unroll
            for (int ks = 0; ks < 2; ks++) {
                uint32_t t4[4];
                ldsm4(t4, tbase + (b_n + ntp * 16) * 80 + (ks * 16 + b_kof) * 2);
                bF[ntp * 2 + 0][ks][0] = t4[0]; bF[ntp * 2 + 0][ks][1] = t4[1];
                bF[ntp * 2 + 1][ks][0] = t4[2]; bF[ntp * 2 + 1][ks][1] = t4[3];
            }
    };
    auto mma_all = [&]() {
        #pragma unroll
        for (int ks = 0; ks < 2; ks++)
            #pragma unroll
            for (int mt = 0; mt < 2; mt++)
                #pragma unroll
                for (int nt = 0; nt < 8; nt++)
                    mma_f16(acc[mt][nt], aF[mt][ks], bF[nt][ks]);
    };

    load_chunk(0);
    load_chunk(1);
    for (int kc = 0; kc < nk; kc++) {
        CP_WAIT(1);
        __syncthreads();
        load_chunk(kc + 2);

        const uint32_t base = sbase + (kc % 3) * BUFB1;
        loadA(base);
        loadB(base + TILEB);
        mma_all();
    }

    #pragma unroll
    for (int mt = 0; mt < 2; mt++) {
        #pragma unroll
        for (int nt = 0; nt < 8; nt++) {
            const int row = bm + wm * 32 + mt * 16 + (lane >> 2);
            const int col = bn + wn * 64 + nt * 8 + ((lane & 3) << 1);
            const float bi0 = bias[col], bi1 = bias[col + 1];
            float o00 = acc[mt][nt][0] + bi0, o01 = acc[mt][nt][1] + bi1;
            float o10 = acc[mt][nt][2] + bi0, o11 = acc[mt][nt][3] + bi1;
            if (RELU) {
                o00 = fmaxf(o00, 0.f); o01 = fmaxf(o01, 0.f);
                o10 = fmaxf(o10, 0.f); o11 = fmaxf(o11, 0.f);
            }
            const size_t i0 = (size_t)row * N + col;
            const size_t i1 = (size_t)(row + 8) * N + col;
            if (EMITH) {
                *(uint32_t*)(Ch + i0) = pack2(o00, o01);
                *(uint32_t*)(Ch + i1) = pack2(o10, o11);
            } else {
                *(float2*)(C + i0) = make_float2(o00, o01);
                *(float2*)(C + i1) = make_float2(o10, o11);
            }
        }
    }
}

// ---------------------------------------------------------------------------
// Fused scores GEMM (HMMA, single-pass), fp16 output: per (b,h):
//   AWS[i, j]     = Q_h[i,:] . K_h[j,:]       (j < 512)
//   AWS[i, 512+e] = Q_h[i,:] . pos_emb[e,:]   (e < 129; pad rows zero)
// ---------------------------------------------------------------------------
constexpr int QK_LDS = 72;
constexpr int QK_T   = 128 * QK_LDS * 2;     // 18432
constexpr int QK_SMEM = 2 * QK_T;            // 36864 B

__global__ void __launch_bounds__(256)
qk_scores()
{
    extern __shared__ char sm[];
    const uint32_t sA = smem_u32(sm);
    const uint32_t sB = sA + QK_T;
    const int tid = threadIdx.x;
    const int wid = tid >> 5, lane = tid & 31;
    const int wm = wid & 3, wn = wid >> 2;
    const int bn = blockIdx.x * 128, bm = blockIdx.y * 128;
    const int bh = blockIdx.z, b = bh >> 4, h = bh & 15;

    {
        const int r0 = tid >> 3, sg = (tid & 7) << 3;
        #pragma unroll
        for (int it = 0; it < 4; it++) {
            const int r = r0 + it * 32;
            const uint32_t off = (r * QK_LDS + sg) * 2;
            cpasync16(sA + off, g_qkvh + (size_t)(b * Sc + bm + r) * E3 + h * HDc + sg);
            const int gr = bn + r;
            const __half* bph;
            if (gr < Sc) {
                bph = g_qkvh + (size_t)(b * Sc + gr) * E3 + Ec + h * HDc + sg;
            } else {
                bph = g_peh + (size_t)(gr - Sc) * HDc + sg;
            }
            cpasync16(sB + off, bph);
        }
        CP_COMMIT(); CP_WAIT(0);
        __syncthreads();
    }

    float acc[2][8][4];
    #pragma unroll
    for (int mt = 0; mt < 2; mt++)
        #pragma unroll
        for (int nt = 0; nt < 8; nt++)
            #pragma unroll
            for (int i = 0; i < 4; i++) acc[mt][nt][i] = 0.f;

    uint32_t aF[2][2][4], bF[8][2][2];
    const int a_row = wm * 32 + (lane & 15);
    const int a_kof = (lane >> 4) << 3;
    const int b_n   = wn * 64 + (lane & 7) + ((lane & 16) >> 1);
    const int b_kof = ((lane >> 3) & 1) << 3;

    auto loadA = [&](int k0) {
        #pragma unroll
        for (int mt = 0; mt < 2; mt++)
            #pragma unroll
            for (int ks = 0; ks < 2; ks++)
                ldsm4(aF[mt][ks], sA + ((a_row + mt * 16) * QK_LDS + k0 + ks * 16 + a_kof) * 2);
    };
    auto loadB = [&](int k0) {
        #pragma unroll
        for (int ntp = 0; ntp < 4; ntp++)
            #pragma unroll
            for (int ks = 0; ks < 2; ks++) {
                uint32_t t4[4];
                ldsm4(t4, sB + ((b_n + ntp * 16) * QK_LDS + k0 + ks * 16 + b_kof) * 2);
                bF[ntp * 2 + 0][ks][0] = t4[0]; bF[ntp * 2 + 0][ks][1] = t4[1];
                bF[ntp * 2 + 1][ks][0] = t4[2]; bF[ntp * 2 + 1][ks][1] = t4[3];
            }
    };
    auto mma_all = [&]() {
        #pragma unroll
        for (int ks = 0; ks < 2; ks++)
            #pragma unroll
            for (int mt = 0; mt < 2; mt++)
                #pragma unroll
                for (int nt = 0; nt < 8; nt++)
                    mma_f16(acc[mt][nt], aF[mt][ks], bF[nt][ks]);
    };

    #pragma unroll
    for (int kg = 0; kg < 2; kg++) {
        const int k0 = kg * 32;
        loadA(k0);
        loadB(k0);
        mma_all();
    }

    #pragma unroll
    for (int mt = 0; mt < 2; mt++) {
        #pragma unroll
        for (int nt = 0; nt < 8; nt++) {
            const int row = bm + wm * 32 + mt * 16 + (lane >> 2);
            const int col = bn + wn * 64 + nt * 8 + ((lane & 3) << 1);
            if (col < SE) {
                const size_t base = (size_t)(bh * Sc + row) * SE + col;
                *(uint32_t*)(g_aws + base)             = pack2(acc[mt][nt][0], acc[mt][nt][1]);
                *(uint32_t*)(g_aws + base + 8ull * SE) = pack2(acc[mt][nt][2], acc[mt][nt][3]);
            }
        }
    }
}

// ---------------------------------------------------------------------------
// Per-head V^T build (hi only)
// ---------------------------------------------------------------------------
__global__ void vt_build()
{
    __shared__ __half th[32][33];
    const int jt = blockIdx.x, dt = blockIdx.y, bh = blockIdx.z;
    const int b = bh >> 4, h = bh & 15;
    const int j0 = jt * 32, d0 = dt * 32;
    const int tx = threadIdx.x, ty = threadIdx.y;

    #pragma unroll
    for (int k = 0; k < 4; k++) {
        const int j = j0 + ty + k * 8;
        const int d = d0 + tx;
        __half vh;
        if (j < Sc) {
            vh = g_qkvh[(size_t)(b * Sc + j) * E3 + 2 * Ec + h * HDc + d];
        } else if (j < Sc + NEc) {
            vh = g_peh[(size_t)(j - Sc) * HDc + d];
        } else {
            vh = __float2half_rn(0.f);
        }
        th[ty + k * 8][tx] = vh;
    }
    __syncthreads();
    #pragma unroll
    for (int k = 0; k < 4; k++) {
        const int d = d0 + ty + k * 8;
        const int j = j0 + tx;
        g_vth[(size_t)bh * HDc * SE + (size_t)d * SE + j] = th[tx][ty + k * 8];
    }
}

// ---------------------------------------------------------------------------
// AV GEMM (HMMA, single-pass): A = aw hi, B = vt hi. 3-stage pipeline, BK=32.
// ---------------------------------------------------------------------------
constexpr int AV_AT = 128 * LDSp * 2;          // 10240
constexpr int AV_BT = 64 * LDSp * 2;           // 5120
constexpr int AV_ST = AV_AT + AV_BT;           // 15360
constexpr int AV_SMEM = 3 * AV_ST;             // 46080

__global__ void __launch_bounds__(256)
av_mma()
{
    extern __shared__ char sm[];
    const uint32_t sbase = smem_u32(sm);
    const int tid = threadIdx.x;
    const int wid = tid >> 5, lane = tid & 31;
    const int bm = blockIdx.x * 128;
    const int bh = blockIdx.y, b = bh >> 4, h = bh & 15;
    const int nk = SE / 32;   // 21

    auto load_chunk = [&](int kc) {
        if (kc < nk) {
            const uint32_t base = sbase + (kc % 3) * AV_ST;
            const int k0 = kc * 32;
            const int sg = (tid & 3) << 3;
            #pragma unroll
            for (int it = 0; it < 2; it++) {
                const int r = (tid >> 2) + it * 64;
                cpasync16(base + r * 80 + sg * 2,
                          g_awh + (size_t)(bh * Sc + bm + r) * SE + k0 + sg);
            }
            {
                const int r = tid >> 2;
                if (r < 64) {
                    cpasync16(base + AV_AT + r * 80 + sg * 2,
                              g_vth + (size_t)bh * HDc * SE + (size_t)r * SE + k0 + sg);
                }
            }
        }
        CP_COMMIT();
    };

    float acc[8][4];
    #pragma unroll
    for (int nt = 0; nt < 8; nt++)
        #pragma unroll
        for (int i = 0; i < 4; i++) acc[nt][i] = 0.f;

    uint32_t aF[2][4], bF[8][2][2];
    const int a_row = wid * 16 + (lane & 15);
    const int a_kof = (lane >> 4) << 3;
    const int b_n   = (lane & 7) + ((lane & 16) >> 1);
    const int b_kof = ((lane >> 3) & 1) << 3;

    auto loadA = [&](uint32_t tb) {
        #pragma unroll
        for (int ks = 0; ks < 2; ks++)
            ldsm4(aF[ks], tb + (a_row * 80) + (ks * 16 + a_kof) * 2);
    };
    auto loadB = [&](uint32_t tb) {
        #pragma unroll
        for (int ntp = 0; ntp < 4; ntp++)
            #pragma unroll
            for (int ks = 0; ks < 2; ks++) {
                uint32_t t4[4];
                ldsm4(t4, tb + (b_n + ntp * 16) * 80 + (ks * 16 + b_kof) * 2);
                bF[ntp * 2 + 0][ks][0] = t4[0]; bF[ntp * 2 + 0][ks][1] = t4[1];
                bF[ntp * 2 + 1][ks][0] = t4[2]; bF[ntp * 2 + 1][ks][1] = t4[3];
            }
    };
    auto mma_all = [&]() {
        #pragma unroll
        for (int ks = 0; ks < 2; ks++)
            #pragma unroll
            for (int nt = 0; nt < 8; nt++)
                mma_f16(acc[nt], aF[ks], bF[nt][ks]);
    };

    load_chunk(0);
    load_chunk(1);
    for (int kc = 0; kc < nk; kc++) {
        CP_WAIT(1);
        __syncthreads();
        load_chunk(kc + 2);
        const uint32_t base = sbase + (kc % 3) * AV_ST;
        loadA(base);
        loadB(base + AV_AT);
        mma_all();
    }

    #pragma unroll
    for (int nt = 0; nt < 8; nt++) {
        const int row = bm + wid * 16 + (lane >> 2);
        const int col = nt * 8 + ((lane & 3) << 1);
        const size_t i0 = (size_t)(b * Sc + row) * Ec + h * HDc + col;
        const size_t i1 = (size_t)(b * Sc + row + 8) * Ec + h * HDc + col;
        *(uint32_t*)(g_ah + i0) = pack2(acc[nt][0], acc[nt][1]);
        *(uint32_t*)(g_ah + i1) = pack2(acc[nt][2], acc[nt][3]);
    }
}

// ---------------------------------------------------------------------------
// Merged prep: 6 weight transposes + pe + x-round + bias concat, one launch.
// Tiles: wq[0,1024) wk[1024,2048) wv[2048,3072) wo[3072,4096)
// ff1[4096,8192) ff2[8192,12288) pe[12288,12352) x[12352,20544) bias[20544,20556)
// ---------------------------------------------------------------------------
__device__ __forceinline__ void tr_tile(
    const float* __restrict__ W, int N, __half* __restrict__ dst,
    int rowOff, int ldo, int idx, int xTiles, int tx, int ty)
{
    __shared__ float t[32][33];
    const int n0 = (idx % xTiles) * 32;
    const int k0 = (idx / xTiles) * 32;
    #pragma unroll
    for (int j = 0; j < 32; j += 8)
        t[ty + j][tx] = W[(size_t)(k0 + ty + j) * N + n0 + tx];
    __syncthreads();
    #pragma unroll
    for (int j = 0; j < 32; j += 8)
        dst[(size_t)(rowOff + n0 + ty + j) * ldo + k0 + tx] = __float2half_rn(t[tx][ty + j]);
}

__global__ void __launch_bounds__(256) prep_all(
    const float* __restrict__ wq, const float* __restrict__ wk,
    const float* __restrict__ wv, const float* __restrict__ wo,
    const float* __restrict__ ff1, const float* __restrict__ ff2,
    const float* __restrict__ pos_emb, const float* __restrict__ x,
    const float* __restrict__ bq, const float* __restrict__ bk,
    const float* __restrict__ bv)
{
    const int bidx = blockIdx.x;
    const int tid = threadIdx.x;
    const int tx = tid & 31, ty = tid >> 5;
    if (bidx < 1024)       tr_tile(wq,  Ec,  g_W3h, 0,      Ec,  bidx,         32,  tx, ty);
    else if (bidx < 2048)  tr_tile(wk,  Ec,  g_W3h, Ec,     Ec,  bidx - 1024,  32,  tx, ty);
    else if (bidx < 3072)  tr_tile(wv,  Ec,  g_W3h, 2 * Ec, Ec,  bidx - 2048,  32,  tx, ty);
    else if (bidx < 4096)  tr_tile(wo,  Ec,  g_Woh, 0,      Ec,  bidx - 3072,  32,  tx, ty);
    else if (bidx < 8192)  tr_tile(ff1, FFc, g_W1h, 0,      Ec,  bidx - 4096,  128, tx, ty);
    else if (bidx < 12288) tr_tile(ff2, Ec,  g_W2h, 0,      FFc, bidx - 8192,  32,  tx, ty);
    else if (bidx < 12352) {
        const int i = (bidx - 12288) * 256 + tid;
        if (i < 256 * HDc) {
            const int e = i >> 6;
            g_peh[i] = __float2half_rn((e < NEc) ? pos_emb[i] : 0.f);
        }
    } else if (bidx < 20544) {
        const int i = (bidx - 12352) * 256 + tid;   // float2 index, n2 = 2M
        const float2 v = ((const float2*)x)[i];
        ((uint32_t*)g_xh)[i] = pack2(v.x, v.y);
    } else {
        const int i = (bidx - 20544) * 256 + tid;
        if (i < Ec) g_b3[i] = bq[i];
        else if (i < 2 * Ec) g_b3[i] = bk[i - Ec];
        else if (i < 3 * Ec) g_b3[i] = bv[i - 2 * Ec];
    }
}

// ---------------------------------------------------------------------------
// Softmax, warp-per-row (fp16 score input)
// ---------------------------------------------------------------------------
__global__ void __launch_bounds__(256) softmax_kernel(
    const float* __restrict__ dist, const int* __restrict__ dt)
{
    __shared__ int dts[Sc];
    __shared__ float bucket[8][NEc + 1];

    const int rg = blockIdx.x, h = blockIdx.y, b = blockIdx.z;
    const int tid = threadIdx.x;
    const int w = tid >> 5, lane = tid & 31;
    const int i = rg * 8 + w;
    const int bh = b * Hc + h;
    const size_t rowbase = (size_t)(bh * Sc + i) * SE;
    const float* drow = dist + ((size_t)b * Sc + i) * Sc;
    float* buck = bucket[w];

    for (int t = tid; t < Sc; t += 256) dts[t] = dt[b * Sc + t];
    for (int t = lane; t < NEc; t += 32) buck[t] = 0.f;
    __syncthreads();

    const int dti = dts[i];

    float s[16];
    int e[16];
    float lmax = -1e30f;
    #pragma unroll
    for (int t = 0; t < 16; t++) {
        const int j = lane + t * 32;
        int rel = dts[j] - dti;
        rel = rel < -64 ? -64 : (rel > 64 ? 64 : rel);
        e[t] = rel + 64;
        const float v = (__half2float(g_aws[rowbase + j])
                         + __half2float(g_aws[rowbase + Sc + e[t]])) * 0.125f
                        + 0.6f * drow[j];
        s[t] = v;
        lmax = fmaxf(lmax, v);
    }
    #pragma unroll
    for (int o = 16; o; o >>= 1) lmax = fmaxf(lmax, __shfl_xor_sync(0xffffffffu, lmax, o));

    float lsum = 0.f;
    #pragma unroll
    for (int t = 0; t < 16; t++) {
        s[t] = __expf(s[t] - lmax);
        lsum += s[t];
    }
    #pragma unroll
    for (int o = 16; o; o >>= 1) lsum += __shfl_xor_sync(0xffffffffu, lsum, o);
    const float inv = 1.f / lsum;

    #pragma unroll
    for (int t = 0; t < 16; t++) {
        const float a = s[t] * inv;
        g_awh[rowbase + lane + t * 32] = __float2half_rn(a);
        atomicAdd(&buck[e[t]], a);
    }
    __syncwarp();
    for (int t = lane; t < SE - Sc; t += 32) {
        g_awh[rowbase + Sc + t] = __float2half_rn((t < NEc) ? buck[t] : 0.f);
    }
}

// ---------------------------------------------------------------------------
// out = LayerNorm(X + R); optional fp16 (hi-only) emission.
// ---------------------------------------------------------------------------
template<int EMIT>
__global__ void __launch_bounds__(256) add_ln_kernel(
    const float* __restrict__ X, const float* __restrict__ Rr,
    const float* __restrict__ gam, const float* __restrict__ bet,
    float* __restrict__ Out, __half* __restrict__ Oh)
{
    __shared__ float sh[Ec];
    __shared__ float red[8];
    const int row = blockIdx.x;
    const int tid = threadIdx.x;
    const float* xr = X + (size_t)row * Ec;
    const float* rr = Rr + (size_t)row * Ec;

    float lsum = 0.f;
    for (int t = tid; t < Ec; t += 256) {
        const float v = xr[t] + rr[t];
        sh[t] = v;
        lsum += v;
    }
    #pragma unroll
    for (int o = 16; o; o >>= 1) lsum += __shfl_xor_sync(0xffffffffu, lsum, o);
    if ((tid & 31) == 0) red[tid >> 5] = lsum;
    __syncthreads();
    float tot = 0.f;
    #pragma unroll
    for (int w = 0; w < 8; w++) tot += red[w];
    const float mu = tot * (1.f / Ec);
    __syncthreads();

    float lvar = 0.f;
    for (int t = tid; t < Ec; t += 256) {
        const float d = sh[t] - mu;
        lvar += d * d;
    }
    #pragma unroll
    for (int o = 16; o; o >>= 1) lvar += __shfl_xor_sync(0xffffffffu, lvar, o);
    if ((tid & 31) == 0) red[tid >> 5] = lvar;
    __syncthreads();
    float vtot = 0.f;
    #pragma unroll
    for (int w = 0; w < 8; w++) vtot += red[w];
    const float inv = rsqrtf(vtot * (1.f / Ec) + 1e-5f);

    float* orow = Out + (size_t)row * Ec;
    for (int t = tid; t < Ec; t += 256) {
        const float v = (sh[t] - mu) * inv * gam[t] + bet[t];
        orow[t] = v;
        if (EMIT) Oh[(size_t)row * Ec + t] = __float2half_rn(v);
    }
}

// ---------------------------------------------------------------------------
extern "C" void kernel_launch(void* const* d_in, const int* in_sizes, int n_in,
                              void* d_out, int out_size)
{
    (void)in_sizes; (void)n_in; (void)out_size;
    const float* x       = (const float*)d_in[0];
    const float* dist    = (const float*)d_in[1];
    const int*   dt      = (const int*)d_in[2];
    const float* pos_emb = (const float*)d_in[3];
    const float* wq_w = (const float*)d_in[4];
    const float* wq_b = (const float*)d_in[5];
    const float* wk_w = (const float*)d_in[6];
    const float* wk_b = (const float*)d_in[7];
    const float* wv_w = (const float*)d_in[8];
    const float* wv_b = (const float*)d_in[9];
    const float* wo_w = (const float*)d_in[10];
    const float* wo_b = (const float*)d_in[11];
    const float* ff1_w = (const float*)d_in[12];
    const float* ff1_b = (const float*)d_in[13];
    const float* ff2_w = (const float*)d_in[14];
    const float* ff2_b = (const float*)d_in[15];
    const float* ln1_g = (const float*)d_in[16];
    const float* ln1_b = (const float*)d_in[17];
    const float* ln2_g = (const float*)d_in[18];
    const float* ln2_b = (const float*)d_in[19];
    float* out = (float*)d_out;

    __half *xh, *W3h, *Woh, *W1h, *W2h;
    __half *qkvh, *ah, *hh, *fh;
    float *b3, *T0, *Hs;
    cudaGetSymbolAddress((void**)&xh, g_xh);
    cudaGetSymbolAddress((void**)&W3h, g_W3h);
    cudaGetSymbolAddress((void**)&Woh, g_Woh);
    cudaGetSymbolAddress((void**)&W1h, g_W1h);
    cudaGetSymbolAddress((void**)&W2h, g_W2h);
    cudaGetSymbolAddress((void**)&qkvh, g_qkvh);
    cudaGetSymbolAddress((void**)&ah, g_ah);
    cudaGetSymbolAddress((void**)&hh, g_hh);
    cudaGetSymbolAddress((void**)&fh, g_fh);
    cudaGetSymbolAddress((void**)&b3, g_b3);
    cudaGetSymbolAddress((void**)&T0, g_t0);
    cudaGetSymbolAddress((void**)&Hs, g_h);

    cudaFuncSetAttribute(mma_gemm<0, 1>, cudaFuncAttributeMaxDynamicSharedMemorySize, MMA_SMEM);
    cudaFuncSetAttribute(mma_gemm<0, 0>, cudaFuncAttributeMaxDynamicSharedMemorySize, MMA_SMEM);
    cudaFuncSetAttribute(mma_gemm<1, 1>, cudaFuncAttributeMaxDynamicSharedMemorySize, MMA_SMEM);
    cudaFuncSetAttribute(qk_scores, cudaFuncAttributeMaxDynamicSharedMemorySize, QK_SMEM);
    cudaFuncSetAttribute(av_mma, cudaFuncAttributeMaxDynamicSharedMemorySize, AV_SMEM);

    dim3 blk(256);
    dim3 tblk(32, 8);

    // merged prep: weights + pe + x-round + bias concat
    prep_all<<<20556, blk>>>(wq_w, wk_w, wv_w, wo_w, ff1_w, ff2_w,
                             pos_emb, x, wq_b, wk_b, wv_b);

    // fused QKV projection (single-pass, BK=32, 3-stage)
    mma_gemm<0, 1><<<dim3(E3 / 128, Mc / 128), blk, MMA_SMEM>>>(
        xh, W3h, b3, nullptr, qkvh, Ec, E3);

    // per-head V^T (+pe^T) staging
    vt_build<<<dim3(SE / 32, 2, 128), tblk>>>();

    // fused scores (single-pass, fp16 out)
    qk_scores<<<dim3(6, 4, 128), blk, QK_SMEM>>>();

    // softmax, warp-per-row (fp16 in)
    softmax_kernel<<<dim3(Sc / 8, Hc, Bc), blk>>>(dist, dt);

    // attn = aw_ext @ vt^T (single-pass)
    av_mma<<<dim3(4, 128), blk, AV_SMEM>>>();

    // output projection
    mma_gemm<0, 0><<<dim3(Ec / 128, Mc / 128), blk, MMA_SMEM>>>(
        ah, Woh, wo_b, T0, nullptr, Ec, Ec);

    // h = LN(x + attn_out), emit fp16 for FF1
    add_ln_kernel<1><<<Mc, blk>>>(x, T0, ln1_g, ln1_b, Hs, hh);

    // FFN (single-pass both)
    mma_gemm<1, 1><<<dim3(FFc / 128, Mc / 128), blk, MMA_SMEM>>>(
        hh, W1h, ff1_b, nullptr, fh, Ec, FFc);
    mma_gemm<0, 0><<<dim3(Ec / 128, Mc / 128), blk, MMA_SMEM>>>(
        fh, W2h, ff2_b, T0, nullptr, FFc, Ec);

    // out = LN(h + ffn)
    add_ln_kernel<0><<<Mc, blk>>>(Hs, T0, ln2_g, ln2_b, out, nullptr);
}